// round 9
// baseline (speedup 1.0000x reference)
#include <cuda_runtime.h>
#include <cuda_fp16.h>
#include <math.h>
#include <stdint.h>

// Problem constants
#define B_SZ   256
#define IN_SZ  512
#define OUT_SZ 512
#define R_SZ   4
#define H_SZ   4608             // (IN+OUT)*R + OUT
#define G4_SZ  (4*H_SZ)         // 18432  (gate columns)
#define NX_SZ  (G4_SZ + OUT_SZ) // 18944  (gates + x@W0^T columns) = 148*128
#define K_TOT  (IN_SZ + H_SZ)   // 5120

// GEMM tile config (fp16 mma.sync m16n8k16) — round-5 best-measured config
#define BM 128
#define BN 128
#define BK 32
#define BKP 40                  // padded row (80 B, conflict-free frag loads)
#define NTHREADS 256
#define NCTAS 296               // == 148 SMs * 2 resident CTAs: one full wave

// Scratch (no cudaMalloc allowed)
__device__ float g_gates[B_SZ * NX_SZ];   // 19.4 MB
__device__ float g_z[B_SZ * R_SZ];
__device__ unsigned int g_bar[2];         // monotonic grid-barrier counters

// ---------------------------------------------------------------------------
__device__ __forceinline__ void mma_f16(float c[4],
                                        uint32_t a0, uint32_t a1, uint32_t a2, uint32_t a3,
                                        uint32_t b0, uint32_t b1) {
    asm volatile(
        "mma.sync.aligned.m16n8k16.row.col.f32.f16.f16.f32 "
        "{%0,%1,%2,%3}, {%4,%5,%6,%7}, {%8,%9}, {%0,%1,%2,%3};"
        : "+f"(c[0]), "+f"(c[1]), "+f"(c[2]), "+f"(c[3])
        : "r"(a0), "r"(a1), "r"(a2), "r"(a3), "r"(b0), "r"(b1));
}

__device__ __forceinline__ uint32_t h2u(__half2 h) {
    return *reinterpret_cast<uint32_t*>(&h);
}

__device__ __forceinline__ float sigm(float v) { return 1.0f / (1.0f + expf(-v)); }

// Monotonic grid barrier: safe because all NCTAS CTAs are co-resident (1 wave),
// and counters only ever increase (graph replays consume epochs of NCTAS each).
__device__ __forceinline__ void grid_barrier(unsigned int* ctr) {
    __syncthreads();
    if (threadIdx.x == 0) {
        __threadfence();
        unsigned int ticket = atomicAdd(ctr, 1u);
        unsigned int target = ticket - (ticket % NCTAS) + NCTAS;
        unsigned int v;
        do {
            asm volatile("ld.acquire.gpu.u32 %0, [%1];" : "=r"(v) : "l"(ctr));
            if (v < target) __nanosleep(128);
        } while (v < target);
    }
    __syncthreads();
}

// ---------------------------------------------------------------------------
// One fused kernel:
//  Phase 0 (GEMM): C[m,n'] row-major [256 x 18944] into g_gates
//    n' < G4:  [x|h0] @ [Wih|Whh]^T + (bih+bhh);  n' >= G4: x @ W0^T
//  barrier
//  Phase A: LSTM elementwise -> h_out/c_out (grid-stride, float4)
//           + z[b,r] dots on 1024 warps (h_new recomputed from gates)
//  barrier
//  Phase B: y[b,o] = xw0 + bias0 + db + sum_r dw1[o,r]*z[r]
// ---------------------------------------------------------------------------
__global__ __launch_bounds__(NTHREADS, 2)
void fused_all(const float* __restrict__ x,  const float* __restrict__ h0,
               const float* __restrict__ c0,
               const float* __restrict__ Wih, const float* __restrict__ Whh,
               const float* __restrict__ bih, const float* __restrict__ bhh,
               const float* __restrict__ W0,  const float* __restrict__ bias0,
               float* __restrict__ y, float* __restrict__ h_out,
               float* __restrict__ c_out)
{
    __shared__ __align__(16) __half As[2][BM][BKP];
    __shared__ __align__(16) __half Bs[2][BN][BKP];

    const int tid = threadIdx.x;
    const int bid = blockIdx.x;
    const int bx  = bid % 148;         // n-tile
    const int by  = bid / 148;         // m-tile

    // ===================== Phase 0: gates GEMM =====================
    {
        const int bm  = by * BM;
        const int bn  = bx * BN;
        const bool isW0 = (bn >= G4_SZ);
        const int NIT = isW0 ? (IN_SZ / BK) : (K_TOT / BK);   // 16 or 160

        const int warp = tid >> 5;
        const int lane = tid & 31;
        const int wm0 = (warp & 3) * 32;
        const int wn0 = (warp >> 2) * 64;
        const int q   = lane & 3;
        const int t8  = lane >> 2;

        float acc[2][8][4];
#pragma unroll
        for (int mi = 0; mi < 2; mi++)
#pragma unroll
            for (int ni = 0; ni < 8; ni++)
#pragma unroll
                for (int e = 0; e < 4; e++) acc[mi][ni][e] = 0.f;

        float4 ra[4], rb[4];

        auto ldg_tile = [&](int t) {
            const int k0 = t * BK;
            const float* baseA; long sA;
            if (k0 < IN_SZ) { baseA = x + (long)bm * IN_SZ + k0; sA = IN_SZ; }
            else            { baseA = h0 + (long)bm * H_SZ + (k0 - IN_SZ); sA = H_SZ; }
#pragma unroll
            for (int j = 0; j < 4; j++) {
                int ch = j * 256 + tid, row = ch >> 3, c = ch & 7;
                ra[j] = *reinterpret_cast<const float4*>(baseA + (long)row * sA + c * 4);
            }
            const float* baseB; long sB;
            if (isW0)            { baseB = W0 + (long)(bn - G4_SZ) * IN_SZ + k0; sB = IN_SZ; }
            else if (k0 < IN_SZ) { baseB = Wih + (long)bn * IN_SZ + k0; sB = IN_SZ; }
            else                 { baseB = Whh + (long)bn * H_SZ + (k0 - IN_SZ); sB = H_SZ; }
#pragma unroll
            for (int j = 0; j < 4; j++) {
                int ch = j * 256 + tid, row = ch >> 3, c = ch & 7;
                rb[j] = *reinterpret_cast<const float4*>(baseB + (long)row * sB + c * 4);
            }
        };

        auto sts_tile = [&](int buf) {
#pragma unroll
            for (int j = 0; j < 4; j++) {
                int ch = j * 256 + tid, row = ch >> 3, c = ch & 7;
                __half2 ha = __floats2half2_rn(ra[j].x, ra[j].y);
                __half2 hb = __floats2half2_rn(ra[j].z, ra[j].w);
                *reinterpret_cast<uint2*>(&As[buf][row][c * 4]) = make_uint2(h2u(ha), h2u(hb));
            }
#pragma unroll
            for (int j = 0; j < 4; j++) {
                int ch = j * 256 + tid, row = ch >> 3, c = ch & 7;
                __half2 ha = __floats2half2_rn(rb[j].x, rb[j].y);
                __half2 hb = __floats2half2_rn(rb[j].z, rb[j].w);
                *reinterpret_cast<uint2*>(&Bs[buf][row][c * 4]) = make_uint2(h2u(ha), h2u(hb));
            }
        };

        auto compute = [&](int buf) {
#pragma unroll
            for (int ks = 0; ks < 2; ks++) {
                const int kb = ks * 16;
                uint32_t a[2][4];
#pragma unroll
                for (int mi = 0; mi < 2; mi++) {
                    int r0 = wm0 + mi * 16 + t8;
                    a[mi][0] = h2u(*reinterpret_cast<const __half2*>(&As[buf][r0    ][kb + 2 * q    ]));
                    a[mi][1] = h2u(*reinterpret_cast<const __half2*>(&As[buf][r0 + 8][kb + 2 * q    ]));
                    a[mi][2] = h2u(*reinterpret_cast<const __half2*>(&As[buf][r0    ][kb + 2 * q + 8]));
                    a[mi][3] = h2u(*reinterpret_cast<const __half2*>(&As[buf][r0 + 8][kb + 2 * q + 8]));
                }
#pragma unroll
                for (int ni = 0; ni < 8; ni++) {
                    int nc = wn0 + ni * 8 + t8;
                    uint32_t b0 = h2u(*reinterpret_cast<const __half2*>(&Bs[buf][nc][kb + 2 * q    ]));
                    uint32_t b1 = h2u(*reinterpret_cast<const __half2*>(&Bs[buf][nc][kb + 2 * q + 8]));
                    mma_f16(acc[0][ni], a[0][0], a[0][1], a[0][2], a[0][3], b0, b1);
                    mma_f16(acc[1][ni], a[1][0], a[1][1], a[1][2], a[1][3], b0, b1);
                }
            }
        };

        ldg_tile(0);
        sts_tile(0);
        __syncthreads();

        int buf = 0;
        for (int t = 1; t < NIT; t++) {
            ldg_tile(t);
            compute(buf);
            sts_tile(buf ^ 1);
            __syncthreads();
            buf ^= 1;
        }
        compute(buf);

#pragma unroll
        for (int ni = 0; ni < 8; ni++) {
            const int n2 = bn + wn0 + ni * 8 + q * 2;
            float bv0 = 0.f, bv1 = 0.f;
            if (!isW0) {
                bv0 = bih[n2] + bhh[n2];
                bv1 = bih[n2 + 1] + bhh[n2 + 1];
            }
#pragma unroll
            for (int mi = 0; mi < 2; mi++) {
                const int row = bm + wm0 + mi * 16 + t8;
                float2 v0 = make_float2(acc[mi][ni][0] + bv0, acc[mi][ni][1] + bv1);
                float2 v1 = make_float2(acc[mi][ni][2] + bv0, acc[mi][ni][3] + bv1);
                *reinterpret_cast<float2*>(g_gates + (long)row * NX_SZ + n2)       = v0;
                *reinterpret_cast<float2*>(g_gates + (long)(row + 8) * NX_SZ + n2) = v1;
            }
        }
    }

    grid_barrier(&g_bar[0]);

    // ===================== Phase A: eltwise + z =====================
    // LSTM elementwise, float4 grid-stride over B*H/4
    for (int i4 = bid * NTHREADS + tid; i4 < B_SZ * H_SZ / 4; i4 += NCTAS * NTHREADS) {
        const int b  = i4 / (H_SZ / 4);
        const int h4 = (i4 - b * (H_SZ / 4)) * 4;
        const float* gb = g_gates + (long)b * NX_SZ;

        float4 gi4 = *reinterpret_cast<const float4*>(gb + h4);
        float4 gf4 = *reinterpret_cast<const float4*>(gb + H_SZ + h4);
        float4 gg4 = *reinterpret_cast<const float4*>(gb + 2 * H_SZ + h4);
        float4 go4 = *reinterpret_cast<const float4*>(gb + 3 * H_SZ + h4);
        float4 c04 = *reinterpret_cast<const float4*>(c0 + (long)b * H_SZ + h4);

        float4 co, ho;
        float c;
        c = sigm(gf4.x) * c04.x + sigm(gi4.x) * tanhf(gg4.x); co.x = c; ho.x = sigm(go4.x) * tanhf(c);
        c = sigm(gf4.y) * c04.y + sigm(gi4.y) * tanhf(gg4.y); co.y = c; ho.y = sigm(go4.y) * tanhf(c);
        c = sigm(gf4.z) * c04.z + sigm(gi4.z) * tanhf(gg4.z); co.z = c; ho.z = sigm(go4.z) * tanhf(c);
        c = sigm(gf4.w) * c04.w + sigm(gi4.w) * tanhf(gg4.w); co.w = c; ho.w = sigm(go4.w) * tanhf(c);

        *reinterpret_cast<float4*>(c_out + (long)b * H_SZ + h4) = co;
        *reinterpret_cast<float4*>(h_out + (long)b * H_SZ + h4) = ho;
    }

    // z[b,r] = dot(h_new[dw2 region], x[b,:]) — recompute h_new from gates
    {
        const int gw = bid * (NTHREADS / 32) + (tid >> 5);   // global warp id
        const int lane = tid & 31;
        if (gw < B_SZ * R_SZ) {
            const int b = gw >> 2, r = gw & 3;
            const float* gb = g_gates + (long)b * NX_SZ;
            const float* xb = x + b * IN_SZ;
            float s = 0.f;
            for (int i = lane; i < IN_SZ; i += 32) {
                const int hh = OUT_SZ * R_SZ + r * IN_SZ + i;
                float gi = sigm(gb[hh]);
                float gf = sigm(gb[H_SZ + hh]);
                float gg = tanhf(gb[2 * H_SZ + hh]);
                float go = sigm(gb[3 * H_SZ + hh]);
                float cc = gf * c0[(long)b * H_SZ + hh] + gi * gg;
                float hn = go * tanhf(cc);
                s = fmaf(hn, xb[i], s);
            }
#pragma unroll
            for (int off = 16; off; off >>= 1) s += __shfl_xor_sync(0xffffffffu, s, off);
            if (lane == 0) g_z[b * R_SZ + r] = s;
        }
    }

    grid_barrier(&g_bar[1]);

    // ===================== Phase B: y =====================
    for (int idx = bid * NTHREADS + tid; idx < B_SZ * OUT_SZ; idx += NCTAS * NTHREADS) {
        const int b = idx >> 9;
        const int o = idx & 511;
        const float* h = h_out + (long)b * H_SZ;
        float v = g_gates[(long)b * NX_SZ + G4_SZ + o] + bias0[o]
                + h[OUT_SZ * R_SZ + IN_SZ * R_SZ + o];
        float4 w1 = *reinterpret_cast<const float4*>(h + o * R_SZ);
        const float* zb = g_z + b * R_SZ;
        v = fmaf(w1.x, zb[0], v);
        v = fmaf(w1.y, zb[1], v);
        v = fmaf(w1.z, zb[2], v);
        v = fmaf(w1.w, zb[3], v);
        y[idx] = v;
    }
}

// ---------------------------------------------------------------------------
extern "C" void kernel_launch(void* const* d_in, const int* in_sizes, int n_in,
                              void* d_out, int out_size)
{
    const float* x     = (const float*)d_in[0];
    const float* h0    = (const float*)d_in[1];
    const float* c0    = (const float*)d_in[2];
    const float* Wih   = (const float*)d_in[3];
    const float* Whh   = (const float*)d_in[4];
    const float* bih   = (const float*)d_in[5];
    const float* bhh   = (const float*)d_in[6];
    const float* W0    = (const float*)d_in[7];
    const float* bias0 = (const float*)d_in[8];

    float* y     = (float*)d_out;                 // [B, OUT]
    float* h_out = y + B_SZ * OUT_SZ;             // [B, H]
    float* c_out = h_out + B_SZ * H_SZ;           // [B, H]

    fused_all<<<NCTAS, NTHREADS>>>(x, h0, c0, Wih, Whh, bih, bhh, W0, bias0,
                                   y, h_out, c_out);
}

// round 10
// speedup vs baseline: 1.1207x; 1.1207x over previous
#include <cuda_runtime.h>
#include <cuda_fp16.h>
#include <math.h>
#include <stdint.h>

// Problem constants
#define B_SZ   256
#define IN_SZ  512
#define OUT_SZ 512
#define R_SZ   4
#define H_SZ   4608             // (IN+OUT)*R + OUT
#define G4_SZ  (4*H_SZ)         // 18432  (gate columns)
#define NX_SZ  (G4_SZ + OUT_SZ) // 18944  (gates + x@W0^T columns) = 148*128
#define K_TOT  (IN_SZ + H_SZ)   // 5120

// GEMM tile config (fp16 mma.sync m16n8k16) — round-5 measured champion
#define BM 128
#define BN 128
#define BK 32                   // 32 halves of k per stage
#define BKP 40                  // padded row (80 B: 16B-aligned, conflict-free)
#define NTHREADS 256

// Scratch (no cudaMalloc allowed)
__device__ float g_gates[B_SZ * NX_SZ];   // 19.4 MB
__device__ float g_z[B_SZ * R_SZ];

// ---------------------------------------------------------------------------
__device__ __forceinline__ void mma_f16(float c[4],
                                        uint32_t a0, uint32_t a1, uint32_t a2, uint32_t a3,
                                        uint32_t b0, uint32_t b1) {
    asm volatile(
        "mma.sync.aligned.m16n8k16.row.col.f32.f16.f16.f32 "
        "{%0,%1,%2,%3}, {%4,%5,%6,%7}, {%8,%9}, {%0,%1,%2,%3};"
        : "+f"(c[0]), "+f"(c[1]), "+f"(c[2]), "+f"(c[3])
        : "r"(a0), "r"(a1), "r"(a2), "r"(a3), "r"(b0), "r"(b1));
}

__device__ __forceinline__ uint32_t h2u(__half2 h) {
    return *reinterpret_cast<uint32_t*>(&h);
}

// ---------------------------------------------------------------------------
// Kernel 1: C[m, n'] row-major [256 x 18944] into g_gates:
//   n' < G4:  [x|h0] @ [Wih|Whh]^T + (bih+bhh)
//   n' >= G4: x @ W0^T   (K loop only over k<512)
// fp16 mma.sync, 128x128x32 stages, 8 warps of 32x64, double-buffered smem.
// (byte-identical to the 225.4us round-5 champion)
// ---------------------------------------------------------------------------
__global__ __launch_bounds__(NTHREADS, 2)
void gates_gemm(const float* __restrict__ x,  const float* __restrict__ h0,
                const float* __restrict__ Wih, const float* __restrict__ Whh,
                const float* __restrict__ bih, const float* __restrict__ bhh,
                const float* __restrict__ W0)
{
    __shared__ __align__(16) __half As[2][BM][BKP];
    __shared__ __align__(16) __half Bs[2][BN][BKP];

    const int tid = threadIdx.x;
    const int bm  = blockIdx.y * BM;
    const int bn  = blockIdx.x * BN;
    const bool isW0 = (bn >= G4_SZ);                      // block-uniform
    const int NIT = isW0 ? (IN_SZ / BK) : (K_TOT / BK);   // 16 or 160

    const int warp = tid >> 5;
    const int lane = tid & 31;
    const int wm0 = (warp & 3) * 32;   // warp m-strip
    const int wn0 = (warp >> 2) * 64;  // warp n-strip
    const int q   = lane & 3;
    const int t8  = lane >> 2;

    float acc[2][8][4];
#pragma unroll
    for (int mi = 0; mi < 2; mi++)
#pragma unroll
        for (int ni = 0; ni < 8; ni++)
#pragma unroll
            for (int e = 0; e < 4; e++) acc[mi][ni][e] = 0.f;

    float4 ra[4], rb[4];

    auto ldg_tile = [&](int t) {
        const int k0 = t * BK;
        const float* baseA; long sA;
        if (k0 < IN_SZ) { baseA = x + (long)bm * IN_SZ + k0; sA = IN_SZ; }
        else            { baseA = h0 + (long)bm * H_SZ + (k0 - IN_SZ); sA = H_SZ; }
#pragma unroll
        for (int j = 0; j < 4; j++) {
            int ch = j * 256 + tid, row = ch >> 3, c = ch & 7;
            ra[j] = *reinterpret_cast<const float4*>(baseA + (long)row * sA + c * 4);
        }
        const float* baseB; long sB;
        if (isW0)            { baseB = W0 + (long)(bn - G4_SZ) * IN_SZ + k0; sB = IN_SZ; }
        else if (k0 < IN_SZ) { baseB = Wih + (long)bn * IN_SZ + k0; sB = IN_SZ; }
        else                 { baseB = Whh + (long)bn * H_SZ + (k0 - IN_SZ); sB = H_SZ; }
#pragma unroll
        for (int j = 0; j < 4; j++) {
            int ch = j * 256 + tid, row = ch >> 3, c = ch & 7;
            rb[j] = *reinterpret_cast<const float4*>(baseB + (long)row * sB + c * 4);
        }
    };

    auto sts_tile = [&](int buf) {
#pragma unroll
        for (int j = 0; j < 4; j++) {
            int ch = j * 256 + tid, row = ch >> 3, c = ch & 7;
            __half2 ha = __floats2half2_rn(ra[j].x, ra[j].y);
            __half2 hb = __floats2half2_rn(ra[j].z, ra[j].w);
            *reinterpret_cast<uint2*>(&As[buf][row][c * 4]) = make_uint2(h2u(ha), h2u(hb));
        }
#pragma unroll
        for (int j = 0; j < 4; j++) {
            int ch = j * 256 + tid, row = ch >> 3, c = ch & 7;
            __half2 ha = __floats2half2_rn(rb[j].x, rb[j].y);
            __half2 hb = __floats2half2_rn(rb[j].z, rb[j].w);
            *reinterpret_cast<uint2*>(&Bs[buf][row][c * 4]) = make_uint2(h2u(ha), h2u(hb));
        }
    };

    auto compute = [&](int buf) {
#pragma unroll
        for (int ks = 0; ks < 2; ks++) {
            const int kb = ks * 16;
            uint32_t a[2][4];
#pragma unroll
            for (int mi = 0; mi < 2; mi++) {
                int r0 = wm0 + mi * 16 + t8;
                a[mi][0] = h2u(*reinterpret_cast<const __half2*>(&As[buf][r0    ][kb + 2 * q    ]));
                a[mi][1] = h2u(*reinterpret_cast<const __half2*>(&As[buf][r0 + 8][kb + 2 * q    ]));
                a[mi][2] = h2u(*reinterpret_cast<const __half2*>(&As[buf][r0    ][kb + 2 * q + 8]));
                a[mi][3] = h2u(*reinterpret_cast<const __half2*>(&As[buf][r0 + 8][kb + 2 * q + 8]));
            }
#pragma unroll
            for (int ni = 0; ni < 8; ni++) {
                int nc = wn0 + ni * 8 + t8;
                uint32_t b0 = h2u(*reinterpret_cast<const __half2*>(&Bs[buf][nc][kb + 2 * q    ]));
                uint32_t b1 = h2u(*reinterpret_cast<const __half2*>(&Bs[buf][nc][kb + 2 * q + 8]));
                mma_f16(acc[0][ni], a[0][0], a[0][1], a[0][2], a[0][3], b0, b1);
                mma_f16(acc[1][ni], a[1][0], a[1][1], a[1][2], a[1][3], b0, b1);
            }
        }
    };

    // prologue
    ldg_tile(0);
    sts_tile(0);
    __syncthreads();

    int buf = 0;
    for (int t = 1; t < NIT; t++) {
        ldg_tile(t);
        compute(buf);
        sts_tile(buf ^ 1);
        __syncthreads();
        buf ^= 1;
    }
    compute(buf);

    // epilogue: + bias for gate columns, store fp32
#pragma unroll
    for (int ni = 0; ni < 8; ni++) {
        const int n2 = bn + wn0 + ni * 8 + q * 2;
        float bv0 = 0.f, bv1 = 0.f;
        if (!isW0) {
            bv0 = bih[n2] + bhh[n2];
            bv1 = bih[n2 + 1] + bhh[n2 + 1];
        }
#pragma unroll
        for (int mi = 0; mi < 2; mi++) {
            const int row = bm + wm0 + mi * 16 + t8;
            float2 v0 = make_float2(acc[mi][ni][0] + bv0, acc[mi][ni][1] + bv1);
            float2 v1 = make_float2(acc[mi][ni][2] + bv0, acc[mi][ni][3] + bv1);
            *reinterpret_cast<float2*>(g_gates + (long)row * NX_SZ + n2)       = v0;
            *reinterpret_cast<float2*>(g_gates + (long)(row + 8) * NX_SZ + n2) = v1;
        }
    }
}

// ---------------------------------------------------------------------------
// Kernel 2: LSTM elementwise (float4) -> h_new, c_new, PLUS z dots.
// Grid covers B*H/4 elements with 256-thread blocks (1152 blocks);
// the first 128 blocks additionally compute one (b, r) z-dot per 2 warps
// by recomputing h_new from gates (bit-identical fp32 expressions).
// ---------------------------------------------------------------------------
__device__ __forceinline__ float sigm(float v) { return 1.0f / (1.0f + expf(-v)); }

__global__ __launch_bounds__(256)
void lstm_eltwise_z(const float* __restrict__ c0, const float* __restrict__ x,
                    float* __restrict__ h_out, float* __restrict__ c_out)
{
    const int idx = blockIdx.x * blockDim.x + threadIdx.x;   // over B*H/4
    if (idx < B_SZ * H_SZ / 4) {
        const int b  = idx / (H_SZ / 4);
        const int h4 = (idx - b * (H_SZ / 4)) * 4;
        const float* gb = g_gates + (long)b * NX_SZ;

        float4 gi4 = *reinterpret_cast<const float4*>(gb + h4);
        float4 gf4 = *reinterpret_cast<const float4*>(gb + H_SZ + h4);
        float4 gg4 = *reinterpret_cast<const float4*>(gb + 2 * H_SZ + h4);
        float4 go4 = *reinterpret_cast<const float4*>(gb + 3 * H_SZ + h4);
        float4 c04 = *reinterpret_cast<const float4*>(c0 + (long)b * H_SZ + h4);

        float4 co, ho;
        float c;
        c = sigm(gf4.x) * c04.x + sigm(gi4.x) * tanhf(gg4.x); co.x = c; ho.x = sigm(go4.x) * tanhf(c);
        c = sigm(gf4.y) * c04.y + sigm(gi4.y) * tanhf(gg4.y); co.y = c; ho.y = sigm(go4.y) * tanhf(c);
        c = sigm(gf4.z) * c04.z + sigm(gi4.z) * tanhf(gg4.z); co.z = c; ho.z = sigm(go4.z) * tanhf(c);
        c = sigm(gf4.w) * c04.w + sigm(gi4.w) * tanhf(gg4.w); co.w = c; ho.w = sigm(go4.w) * tanhf(c);

        *reinterpret_cast<float4*>(c_out + (long)b * H_SZ + h4) = co;
        *reinterpret_cast<float4*>(h_out + (long)b * H_SZ + h4) = ho;
    }

    // z-dots: 1024 (b,r) pairs, one per 2 warps of the first 128 blocks.
    // Recomputes h_new from gates (identical fp32 ops -> identical values).
    const int gw = (blockIdx.x * 256 + threadIdx.x) >> 6;   // 64-thread group id
    if (gw < B_SZ * R_SZ) {
        const int lane64 = threadIdx.x & 63;
        const int b = gw >> 2, r = gw & 3;
        const float* gb = g_gates + (long)b * NX_SZ;
        const float* xb = x + b * IN_SZ;
        float s = 0.f;
        for (int i = lane64; i < IN_SZ; i += 64) {
            const int hh = OUT_SZ * R_SZ + r * IN_SZ + i;
            float gi = sigm(gb[hh]);
            float gf = sigm(gb[H_SZ + hh]);
            float gg = tanhf(gb[2 * H_SZ + hh]);
            float go = sigm(gb[3 * H_SZ + hh]);
            float cc = gf * c0[(long)b * H_SZ + hh] + gi * gg;
            float hn = go * tanhf(cc);
            s = fmaf(hn, xb[i], s);
        }
        // reduce across the 64-thread group (2 warps) via shuffles + smem
        __shared__ float red[4];     // 4 groups of 64 per 256-thread block
#pragma unroll
        for (int off = 16; off; off >>= 1) s += __shfl_xor_sync(0xffffffffu, s, off);
        const int grp = (threadIdx.x >> 6);
        if ((threadIdx.x & 63) == 0) red[grp] = s;          // warp 0 of group
        __syncthreads();
        if ((threadIdx.x & 63) == 32 && (threadIdx.x & 31) == 0)
            atomicAdd(&g_z[gw & (B_SZ * R_SZ - 1)], 0.f);   // no-op ordering aid
        if ((threadIdx.x & 63) == 32) {
            // lane 0 of second warp adds its partial
        }
        // simpler: second warp's lane0 adds via smem
        if ((threadIdx.x & 31) == 0 && (threadIdx.x & 32)) {
            atomicAdd(&red[grp], s);
        }
        __syncthreads();
        if ((threadIdx.x & 63) == 0) g_z[gw] = red[grp];
    }
}

// ---------------------------------------------------------------------------
// Kernel 3: y[b,o] = xw0[b,o] + bias0[o] + db[b,o] + sum_r dw1[b,o,r]*z[b,r]
// ---------------------------------------------------------------------------
__global__ __launch_bounds__(256)
void y_final(const float* __restrict__ hn, const float* __restrict__ bias0,
             float* __restrict__ y)
{
    int idx = blockIdx.x * blockDim.x + threadIdx.x;   // over B*OUT
    if (idx >= B_SZ * OUT_SZ) return;
    int b = idx >> 9;
    int o = idx & 511;
    const float* h = hn + (long)b * H_SZ;
    float v = g_gates[(long)b * NX_SZ + G4_SZ + o] + bias0[o]
            + h[OUT_SZ * R_SZ + IN_SZ * R_SZ + o];
    float4 w1 = *reinterpret_cast<const float4*>(h + o * R_SZ);
    const float* zb = g_z + b * R_SZ;
    v = fmaf(w1.x, zb[0], v);
    v = fmaf(w1.y, zb[1], v);
    v = fmaf(w1.z, zb[2], v);
    v = fmaf(w1.w, zb[3], v);
    y[idx] = v;
}

// ---------------------------------------------------------------------------
extern "C" void kernel_launch(void* const* d_in, const int* in_sizes, int n_in,
                              void* d_out, int out_size)
{
    const float* x     = (const float*)d_in[0];
    const float* h0    = (const float*)d_in[1];
    const float* c0    = (const float*)d_in[2];
    const float* Wih   = (const float*)d_in[3];
    const float* Whh   = (const float*)d_in[4];
    const float* bih   = (const float*)d_in[5];
    const float* bhh   = (const float*)d_in[6];
    const float* W0    = (const float*)d_in[7];
    const float* bias0 = (const float*)d_in[8];

    float* y     = (float*)d_out;                 // [B, OUT]
    float* h_out = y + B_SZ * OUT_SZ;             // [B, H]
    float* c_out = h_out + B_SZ * H_SZ;           // [B, H]

    dim3 ggrid(NX_SZ / BN, B_SZ / BM);            // (148, 2) = 296 blocks
    gates_gemm<<<ggrid, NTHREADS>>>(x, h0, Wih, Whh, bih, bhh, W0);

    int n4 = B_SZ * H_SZ / 4;                     // 294912 -> 1152 blocks
    lstm_eltwise_z<<<(n4 + 255) / 256, 256>>>(c0, x, h_out, c_out);

    int m = B_SZ * OUT_SZ;
    y_final<<<(m + 255) / 256, 256>>>(h_out, bias0, y);
}